// round 17
// baseline (speedup 1.0000x reference)
#include <cuda_runtime.h>
#include <cuda_fp16.h>
#include <cstdint>

// Problem constants (fixed by the dataset)
#define BB    2
#define N_IN  163842              // even -> node pairs always complete
#define N_OUT 40962
#define CC    128
#define KK    7
#define INV2SIG2 3.125f           // 1 / (2 * 0.4^2)
#define ROW_BYTES   (CC * 2)      // 256 B per fp16 row
#define BATCH_BYTES ((size_t)N_OUT * ROW_BYTES)

// Scratch: fp16 down-pooled features (direct fp16 atomic accumulation),
// fp32 denominators, packed (weight, byte-offset) pairs for the gather.
__device__ __half g_half [BB * N_OUT * CC];   // ~21 MB (L2-resident)
__device__ float  g_denom[N_OUT];
__device__ uint2  g_wo   [N_IN * KK];         // ~9.2 MB: {f32 weight, byte off}

// Bit-cast helpers
__device__ __forceinline__ unsigned int h2_to_u32(half2 h) {
    union { half2 h; unsigned int u; } cvt; cvt.h = h; return cvt.u;
}
__device__ __forceinline__ half2 u32_to_h2(unsigned int u) {
    union { unsigned int u; half2 h; } cvt; cvt.u = u; return cvt.h;
}

// ---------------------------------------------------------------------------
// Denominator scatter: denom[parent[n]] += omega[n]. One thread per node,
// spread scalar atomics (~4-way avg contention) — a few microseconds; runs
// on the weights stream, batch-independent, so it never blocks the feature
// scatter.
// ---------------------------------------------------------------------------
__global__ void __launch_bounds__(256) so3_denom_kernel(
    const float* __restrict__ omega,
    const int*   __restrict__ parent)
{
    int n = blockIdx.x * blockDim.x + threadIdx.x;
    if (n >= N_IN) return;
    asm volatile("red.global.add.f32 [%0], %1;"
                 :: "l"(&g_denom[parent[n]]), "f"(omega[n]) : "memory");
}

// ---------------------------------------------------------------------------
// Feature scatter for ONE batch:
//   down_f16[b, parent[n], :] += f16(x[b, n, :] * omega[n])
// Warp = node pair: lanes 0-15 -> node 2w, lanes 16-31 -> node 2w+1; each
// lane owns 8 channels (2 LDG.128 of x, one red.global.add.v4.f16x2).
// R13-measured-best shape (MLP=2); batch split enables pipelining.
// ---------------------------------------------------------------------------
__global__ void __launch_bounds__(256) so3_scatter_b_kernel(
    const float* __restrict__ x,
    const float* __restrict__ omega,
    const int*   __restrict__ parent,
    int b)
{
    int gtid = blockIdx.x * blockDim.x + threadIdx.x;
    int warp = gtid >> 5;
    int lane = gtid & 31;
    if (warp * 2 >= N_IN) return;

    int n  = warp * 2 + (lane >> 4);   // node of this half-warp
    int hl = lane & 15;                // 8-channel group

    int   p  = parent[n];              // 16-lane broadcast
    float om = omega[n];

    const float4* xr = (const float4*)(x + ((size_t)b * N_IN + n) * CC) + hl * 2;
    float4 a = xr[0];
    float4 c = xr[1];

    uint4 pk;
    pk.x = h2_to_u32(__floats2half2_rn(a.x * om, a.y * om));
    pk.y = h2_to_u32(__floats2half2_rn(a.z * om, a.w * om));
    pk.z = h2_to_u32(__floats2half2_rn(c.x * om, c.y * om));
    pk.w = h2_to_u32(__floats2half2_rn(c.z * om, c.w * om));

    char* dst = (char*)g_half + (size_t)b * BATCH_BYTES
              + (size_t)p * ROW_BYTES + hl * 16;
    asm volatile("red.global.add.noftz.v4.f16x2 [%0], {%1, %2, %3, %4};"
                 :: "l"(dst), "r"(pk.x), "r"(pk.y), "r"(pk.z), "r"(pk.w)
                 : "memory");
}

// ---------------------------------------------------------------------------
// Per-node weight precompute — one THREAD per node (hidden under scatter_b0).
//   w_k   = exp(-delta^2/(2 sig^2)) * mask
//   w''_k = (w_k / max(sum w, 1e-8)) / max(denom[cand_k], 1e-8)
// Emits packed {f32 weight, u32 row byte-offset within a batch}.
// ---------------------------------------------------------------------------
__global__ void __launch_bounds__(256) so3_weights_kernel(
    const float* __restrict__ delta,
    const float* __restrict__ mask,
    const int*   __restrict__ cand)
{
    int n = blockIdx.x * blockDim.x + threadIdx.x;
    if (n >= N_IN) return;

    float w[KK]; int c[KK];
    float wsum = 0.f;
#pragma unroll
    for (int k = 0; k < KK; k++) {
        float d = delta[n * KK + k];
        float m = mask [n * KK + k];
        c[k] = cand[n * KK + k];
        w[k] = __expf(-d * d * INV2SIG2) * m;
        wsum += w[k];
    }
    float inv = 1.0f / fmaxf(wsum, 1e-8f);
#pragma unroll
    for (int k = 0; k < KK; k++) {
        float dn = g_denom[c[k]];
        float wf = (w[k] * inv) / fmaxf(dn, 1e-8f);
        g_wo[n * KK + k] = make_uint2(__float_as_uint(wf),
                                      (unsigned)c[k] * (unsigned)ROW_BYTES);
    }
}

// ---------------------------------------------------------------------------
// Gather for ONE batch: out[b,n,:] = sum_k w''_k * down_f16[b, cand_k, :]
// Warp = node pair (lanes 0-15 node 2w, lanes 16-31 node 2w+1), 8 ch/lane.
// LTS-capped (~13 TB/s of L2 traffic) — byte-minimal at fp16; batch split
// lets scatter_b1 (HBM-bound) run concurrently on the other stream.
// ---------------------------------------------------------------------------
__global__ void __launch_bounds__(256) so3_gather_b_kernel(
    float* __restrict__ out, int b)
{
    int gtid = blockIdx.x * blockDim.x + threadIdx.x;
    int warp = gtid >> 5;
    int lane = gtid & 31;
    if (warp * 2 >= N_IN) return;

    int n  = warp * 2 + (lane >> 4);
    int hl = lane & 15;

    const uint2* __restrict__ wop = g_wo + n * KK;
    const char*  hbase = (const char*)g_half + (size_t)b * BATCH_BYTES
                       + (unsigned)hl * 16u;

    uint2 p[KK];
#pragma unroll
    for (int k = 0; k < KK; k++) p[k] = __ldg(&wop[k]);

    float acc[8];
#pragma unroll
    for (int i = 0; i < 8; i++) acc[i] = 0.f;

#pragma unroll
    for (int k = 0; k < KK; k++) {
        uint4 v = *(const uint4*)(hbase + p[k].y);
        float wk = __uint_as_float(p[k].x);
        float2 f0 = __half22float2(u32_to_h2(v.x));
        float2 f1 = __half22float2(u32_to_h2(v.y));
        float2 f2 = __half22float2(u32_to_h2(v.z));
        float2 f3 = __half22float2(u32_to_h2(v.w));
        acc[0] = fmaf(wk, f0.x, acc[0]);
        acc[1] = fmaf(wk, f0.y, acc[1]);
        acc[2] = fmaf(wk, f1.x, acc[2]);
        acc[3] = fmaf(wk, f1.y, acc[3]);
        acc[4] = fmaf(wk, f2.x, acc[4]);
        acc[5] = fmaf(wk, f2.y, acc[5]);
        acc[6] = fmaf(wk, f3.x, acc[6]);
        acc[7] = fmaf(wk, f3.y, acc[7]);
    }

    float4* o4 = (float4*)(out + ((size_t)(b * N_IN + n) * CC + hl * 8));
    o4[0] = make_float4(acc[0], acc[1], acc[2], acc[3]);
    o4[1] = make_float4(acc[4], acc[5], acc[6], acc[7]);
}

// ---------------------------------------------------------------------------
// Launch: fork-join two-stream pipeline (capture-legal event pattern).
//
//   s0: memset(half) memset(denom) [evM] denom weights | wait(evS0) gather_b0
//       wait(evS1) gather_b1
//   s2: wait(evM) scatter_b0 [evS0] scatter_b1 [evS1]
//
// weights hides under scatter_b0; scatter_b1 (HBM) overlaps gather_b0 (LTS).
// Streams/events are host-side resources created once (no device memory).
// ---------------------------------------------------------------------------
extern "C" void kernel_launch(void* const* d_in, const int* in_sizes, int n_in,
                              void* d_out, int out_size)
{
    const float* x      = (const float*)d_in[0];
    const float* omega  = (const float*)d_in[1];
    const float* delta  = (const float*)d_in[2];
    const float* mask   = (const float*)d_in[3];
    const int*   parent = (const int*)  d_in[4];
    const int*   cand   = (const int*)  d_in[5];
    float*       out    = (float*)d_out;

    static cudaStream_t s2 = []() {
        cudaStream_t s;
        cudaStreamCreateWithFlags(&s, cudaStreamNonBlocking);
        return s;
    }();
    static cudaEvent_t evM = []() {
        cudaEvent_t e; cudaEventCreateWithFlags(&e, cudaEventDisableTiming); return e;
    }();
    static cudaEvent_t evS0 = []() {
        cudaEvent_t e; cudaEventCreateWithFlags(&e, cudaEventDisableTiming); return e;
    }();
    static cudaEvent_t evS1 = []() {
        cudaEvent_t e; cudaEventCreateWithFlags(&e, cudaEventDisableTiming); return e;
    }();

    void* p_half  = nullptr;
    void* p_denom = nullptr;
    cudaGetSymbolAddress(&p_half,  g_half);
    cudaGetSymbolAddress(&p_denom, g_denom);

    const int pair_blocks = ((N_IN / 2) * 32 + 255) / 256;   // warp = node pair
    const int node_blocks = (N_IN + 255) / 256;              // thread = node

    // s0: zero both scratch buffers, then fork.
    cudaMemsetAsync(p_half,  0, sizeof(__half) * BB * N_OUT * CC, 0);
    cudaMemsetAsync(p_denom, 0, sizeof(float) * N_OUT, 0);
    cudaEventRecord(evM, 0);

    // s2: feature scatter, batch 0 then batch 1.
    cudaStreamWaitEvent(s2, evM, 0);
    so3_scatter_b_kernel<<<pair_blocks, 256, 0, s2>>>(x, omega, parent, 0);
    cudaEventRecord(evS0, s2);
    so3_scatter_b_kernel<<<pair_blocks, 256, 0, s2>>>(x, omega, parent, 1);
    cudaEventRecord(evS1, s2);

    // s0: denominator + weights (concurrent with scatter_b0 on s2).
    so3_denom_kernel  <<<node_blocks, 256, 0, 0>>>(omega, parent);
    so3_weights_kernel<<<node_blocks, 256, 0, 0>>>(delta, mask, cand);

    // s0: gather batch 0 (overlaps scatter_b1), then gather batch 1.
    cudaStreamWaitEvent(0, evS0, 0);
    so3_gather_b_kernel<<<pair_blocks, 256, 0, 0>>>(out, 0);
    cudaStreamWaitEvent(0, evS1, 0);
    so3_gather_b_kernel<<<pair_blocks, 256, 0, 0>>>(out, 1);
}